// round 15
// baseline (speedup 1.0000x reference)
#include <cuda_runtime.h>
#include <math_constants.h>
#include <cstdint>

// FilterDetection: score threshold + morphological opening (erode k=4 -> dilate k=4)
// cv2 semantics: erode offsets [-2,+1] (border +inf), dilate offsets [-1,+2]
// (eroded plane outside image = -inf).
//
// Register-pipeline kernel, R3 geometry: each WARP owns a 128-col x 64-row
// strip; 8 warps/CTA, 512 CTAs. Branchless loads, interior/tail split,
// unroll 8. This round: launch_bounds occupancy 4 -> 3 so ptxas gets ~85 regs
// and can front-batch multiple iterations' LDG.128 (MLP up from ~2).

#define CHUNK  128   // columns per warp (32 lanes x float4)
#define RSTRIP 64    // output rows per warp
#define WARPS  8     // warps per CTA
#define N_SCORE 32000

__global__ __launch_bounds__(32 * WARPS, 3)
void open_kernel(const float* __restrict__ mask, float* __restrict__ out,
                 const float* __restrict__ score, float* __restrict__ out_score) {
    const int lane  = threadIdx.x;
    const int warp  = threadIdx.y;
    const int chunk = blockIdx.x;                       // 0..7
    const int c0    = chunk * CHUNK;
    const int r0    = (blockIdx.y * WARPS + warp) * RSTRIP;
    const int col   = c0 + lane * 4;
    const float* img  = mask + (size_t)blockIdx.z * (1024u * 1024u);
    float*       oimg = out  + (size_t)blockIdx.z * (1024u * 1024u);

    // ---- fused score threshold (independent work) ----
    {
        int gtid = (((blockIdx.z * gridDim.y + blockIdx.y) * gridDim.x + blockIdx.x)
                    * (32 * WARPS)) + warp * 32 + lane;
        if (gtid < N_SCORE) {
            float s = score[gtid];
            out_score[gtid] = (s >= 0.5f) ? s : 0.0f;
        }
    }

    const bool leftEdge  = (chunk == 0);
    const bool rightEdge = (chunk == 7);
    const float INF = CUDART_INF_F;

    // Loop-invariant halo address: lane 0 fetches cols c0-4..c0-1, lane 31
    // fetches c0+128..c0+131, interior lanes harmlessly refetch their word.
    const bool pL = (lane == 0)  && !leftEdge;
    const bool pR = (lane == 31) && !rightEdge;
    int haloCol = col;
    if (pL) haloCol = c0 - 4;
    if (pR) haloCol = c0 + CHUNK;

    // pipeline state
    float4 hprev;  float hlprev, hr0prev, hr1prev;
    float4 pring[2]; float plr[2], pr0r[2], pr1r[2];
    float4 gprev;
    float4 sring[2];

    // interior=true: ir and ir-1 are statically known in-bounds (no checks).
    auto step = [&](int t, bool doP, bool doEV, bool doS, bool doOut,
                    bool interior) __attribute__((always_inline)) {
        const int ir  = r0 - 3 + t;
        const int par = t & 1;
        const bool rok = interior || ((unsigned)ir < 1024u);
        const int irc = interior ? ir : min(max(ir, 0), 1023);
        const float* rowp = img + (size_t)irc * 1024;

        // ---- unconditional loads; selects only in non-interior steps ----
        float4 vr = *reinterpret_cast<const float4*>(rowp + col);
        float4 hb = *reinterpret_cast<const float4*>(rowp + haloCol);
        float4 v;
        if (interior) {
            v = vr;
        } else {
            v.x = rok ? vr.x : INF; v.y = rok ? vr.y : INF;
            v.z = rok ? vr.z : INF; v.w = rok ? vr.w : INF;
        }
        const bool okL = interior ? pL : (pL && rok);
        const bool okR = interior ? pR : (pR && rok);
        float xly = okL ? hb.y : INF, xlz = okL ? hb.z : INF, xlw = okL ? hb.w : INF;
        float xrx = okR ? hb.x : INF, xry = okR ? hb.y : INF, xrz = okR ? hb.z : INF;

        // ---- horizontal erode: h_j = min(v_{j-2..j+1}) (van Herk) ----
        float vrx = __shfl_down_sync(0xffffffffu, v.x, 1);
        float vwu = __shfl_up_sync  (0xffffffffu, v.w, 1);
        if (lane == 31) vrx = xrx;
        if (lane == 0)  vwu = xlw;
        float4 q;
        q.x = fminf(v.x, v.y); q.y = fminf(v.y, v.z);
        q.z = fminf(v.z, v.w); q.w = fminf(v.w, vrx);
        float qpz = __shfl_up_sync(0xffffffffu, q.z, 1);
        if (lane == 0) qpz = fminf(xlz, xlw);
        float qpw = fminf(vwu, v.x);                      // q.w of lane-1
        float4 h;
        h.x = fminf(qpz, q.x); h.y = fminf(qpw, q.y);
        h.z = fminf(q.x, q.z); h.w = fminf(q.y, q.w);
        float hl  = fminf(fminf(xly, xlz), qpw);   // h @ col c0-1   (lane 0)
        float hr0 = fminf(q.z, fminf(xrx, xry));   // h @ col c0+128 (lane 31)
        float hr1 = fminf(q.w, fminf(xry, xrz));   // h @ col c0+129 (lane 31)

        if (doP) {
            // vertical erode pairwise
            float4 pn;
            pn.x = fminf(h.x, hprev.x); pn.y = fminf(h.y, hprev.y);
            pn.z = fminf(h.z, hprev.z); pn.w = fminf(h.w, hprev.w);
            float pln  = fminf(hl,  hlprev);
            float pr0n = fminf(hr0, hr0prev);
            float pr1n = fminf(hr1, hr1prev);

            if (doEV) {
                const int e = ir - 1;
                const bool eok = interior || ((unsigned)e < 1024u);
                float4 po = pring[par];
                float4 ev;
                if (interior) {
                    ev.x = fminf(po.x, pn.x); ev.y = fminf(po.y, pn.y);
                    ev.z = fminf(po.z, pn.z); ev.w = fminf(po.w, pn.w);
                } else {
                    ev.x = eok ? fminf(po.x, pn.x) : -INF;
                    ev.y = eok ? fminf(po.y, pn.y) : -INF;
                    ev.z = eok ? fminf(po.z, pn.z) : -INF;
                    ev.w = eok ? fminf(po.w, pn.w) : -INF;
                }
                float evL  = (eok && !leftEdge)  ? fminf(plr[par],  pln)  : -INF;
                float evR0 = (eok && !rightEdge) ? fminf(pr0r[par], pr0n) : -INF;
                float evR1 = (eok && !rightEdge) ? fminf(pr1r[par], pr1n) : -INF;

                // horizontal dilate: g_j = max(ev_{j-1..j+2})
                float evwu = __shfl_up_sync  (0xffffffffu, ev.w, 1);
                float evxd = __shfl_down_sync(0xffffffffu, ev.x, 1);
                float evyd = __shfl_down_sync(0xffffffffu, ev.y, 1);
                if (lane == 0)  evwu = evL;
                if (lane == 31) { evxd = evR0; evyd = evR1; }
                float4 r;
                r.x = fmaxf(evwu, ev.x); r.y = fmaxf(ev.x, ev.y);
                r.z = fmaxf(ev.y, ev.z); r.w = fmaxf(ev.z, ev.w);
                float rnx = fmaxf(ev.w, evxd);
                float rny = fmaxf(evxd, evyd);
                float4 g;
                g.x = fmaxf(r.x, r.z); g.y = fmaxf(r.y, r.w);
                g.z = fmaxf(r.z, rnx); g.w = fmaxf(r.w, rny);

                if (doS) {
                    // vertical dilate pairwise
                    float4 sn;
                    sn.x = fmaxf(g.x, gprev.x); sn.y = fmaxf(g.y, gprev.y);
                    sn.z = fmaxf(g.z, gprev.z); sn.w = fmaxf(g.w, gprev.w);
                    if (doOut) {
                        float4 so = sring[par];
                        float4 o4;
                        o4.x = fmaxf(so.x, sn.x); o4.y = fmaxf(so.y, sn.y);
                        o4.z = fmaxf(so.z, sn.z); o4.w = fmaxf(so.w, sn.w);
                        // threshold (monotone => commutes with opening)
                        o4.x = (o4.x >= 0.5f) ? o4.x : 0.0f;
                        o4.y = (o4.y >= 0.5f) ? o4.y : 0.0f;
                        o4.z = (o4.z >= 0.5f) ? o4.z : 0.0f;
                        o4.w = (o4.w >= 0.5f) ? o4.w : 0.0f;
                        const int o = ir - 3;
                        *reinterpret_cast<float4*>(oimg + (size_t)o * 1024 + col) = o4;
                    }
                    sring[par] = sn;
                }
                gprev = g;
            }
            pring[par] = pn; plr[par] = pln;
            pr0r[par] = pr0n; pr1r[par] = pr1n;
        }
        hprev = h; hlprev = hl; hr0prev = hr0; hr1prev = hr1;
    };

    // pipeline prologue (peeled, checked)
    step(0, false, false, false, false, false);
    step(1, true,  false, false, false, false);
    step(2, true,  false, false, false, false);
    step(3, true,  true,  false, false, false);
    step(4, true,  true,  true,  false, false);
    step(5, true,  true,  true,  false, false);

    // interior steady state: t in [6,65] -> ir in [r0+3, r0+62] subset [3,1022]
    // for every strip (r0 <= 960): no bounds logic at all.
#pragma unroll 8
    for (int t = 6; t < 66; ++t) {
        step(t, true, true, true, true, true);
    }
    // checked tail (bottom strips run past row 1023 here)
#pragma unroll
    for (int t = 66; t < RSTRIP + 6; ++t) {
        step(t, true, true, true, true, false);
    }
}

extern "C" void kernel_launch(void* const* d_in, const int* in_sizes, int n_in,
                              void* d_out, int out_size) {
    const float* score = (const float*)d_in[0];   // 32*1000
    const float* mask  = (const float*)d_in[1];   // 32*1024*1024
    float* out = (float*)d_out;

    float* out_score = out;
    float* out_mask  = out + N_SCORE;

    dim3 grid(1024 / CHUNK, 1024 / (RSTRIP * WARPS), 32);   // (8, 2, 32) = 512 CTAs
    dim3 block(32, WARPS);
    open_kernel<<<grid, block>>>(mask, out_mask, score, out_score);
}

// round 17
// speedup vs baseline: 1.6945x; 1.6945x over previous
#include <cuda_runtime.h>
#include <math_constants.h>
#include <cstdint>

// FilterDetection: score threshold + morphological opening (erode k=4 -> dilate k=4)
// cv2 semantics: erode offsets [-2,+1] (border +inf), dilate offsets [-1,+2]
// (eroded plane outside image = -inf).
//
// Register-pipeline kernel, R3 geometry (WARP = 128-col x 64-row strip,
// 8 warps/CTA, 512 CTAs) + cp.async row prefetch: each row is fetched into a
// per-warp 4-stage SMEM ring at distance 3, so DRAM latency is covered by
// ~3 rows in flight per warp with ZERO register cost. Every lane consumes only
// bytes it wrote itself -> per-thread cp.async.wait_group ordering, no syncs.

#define CHUNK  128   // columns per warp (32 lanes x float4)
#define RSTRIP 64    // output rows per warp
#define WARPS  8     // warps per CTA
#define N_SCORE 32000
#define NSTAGE 4
#define SLOTS  36    // 32 main + 2 halo + 2 pad (576 B/stage)

__global__ __launch_bounds__(32 * WARPS, 4)
void open_kernel(const float* __restrict__ mask, float* __restrict__ out,
                 const float* __restrict__ score, float* __restrict__ out_score) {
    __shared__ float4 buf[WARPS][NSTAGE][SLOTS];

    const int lane  = threadIdx.x;
    const int warp  = threadIdx.y;
    const int chunk = blockIdx.x;                       // 0..7
    const int c0    = chunk * CHUNK;
    const int r0    = (blockIdx.y * WARPS + warp) * RSTRIP;
    const int col   = c0 + lane * 4;
    const float* img  = mask + (size_t)blockIdx.z * (1024u * 1024u);
    float*       oimg = out  + (size_t)blockIdx.z * (1024u * 1024u);

    // ---- fused score threshold (independent work) ----
    {
        int gtid = (((blockIdx.z * gridDim.y + blockIdx.y) * gridDim.x + blockIdx.x)
                    * (32 * WARPS)) + warp * 32 + lane;
        if (gtid < N_SCORE) {
            float s = score[gtid];
            out_score[gtid] = (s >= 0.5f) ? s : 0.0f;
        }
    }

    const bool leftEdge  = (chunk == 0);
    const bool rightEdge = (chunk == 7);
    const float INF = CUDART_INF_F;

    // Halo: lane 0 owns cols c0-4..c0-1 (slot 32), lane 31 owns c0+128..c0+131
    // (slot 33). Each lane reads back only what it wrote.
    const bool pL = (lane == 0)  && !leftEdge;
    const bool pR = (lane == 31) && !rightEdge;
    const bool pOK = pL || pR;
    const int haloCol  = pL ? (c0 - 4) : (c0 + CHUNK);   // used only when pOK
    const int hSlot    = pL ? 32 : (pR ? 33 : lane);

    // Issue cp.async fetch of row for step t into stage t%4. Always clamped.
    auto issueRow = [&](int t) __attribute__((always_inline)) {
        const int ir = r0 - 3 + t;
        const int irc = min(max(ir, 0), 1023);
        const float* rowp = img + (size_t)irc * 1024;
        unsigned sm = (unsigned)__cvta_generic_to_shared(&buf[warp][t & 3][lane]);
        asm volatile("cp.async.cg.shared.global [%0], [%1], 16;"
                     :: "r"(sm), "l"(rowp + col));
        if (pOK) {
            unsigned sh = (unsigned)__cvta_generic_to_shared(&buf[warp][t & 3][hSlot]);
            asm volatile("cp.async.cg.shared.global [%0], [%1], 16;"
                         :: "r"(sh), "l"(rowp + haloCol));
        }
        asm volatile("cp.async.commit_group;" ::: "memory");
    };

    // pipeline state
    float4 hprev;  float hlprev, hr0prev, hr1prev;
    float4 pring[2]; float plr[2], pr0r[2], pr1r[2];
    float4 gprev;
    float4 sring[2];

    // interior=true: ir and ir-1 statically in-bounds (no checks).
    auto step = [&](int t, bool doP, bool doEV, bool doS, bool doOut,
                    bool interior) __attribute__((always_inline)) {
        const int ir  = r0 - 3 + t;
        const int par = t & 1;
        const bool rok = interior || ((unsigned)ir < 1024u);

        // ---- consume prefetched row from SMEM ----
        float4 vr = buf[warp][t & 3][lane];
        float4 hb = buf[warp][t & 3][hSlot];
        float4 v;
        if (interior) {
            v = vr;
        } else {
            v.x = rok ? vr.x : INF; v.y = rok ? vr.y : INF;
            v.z = rok ? vr.z : INF; v.w = rok ? vr.w : INF;
        }
        const bool okL = interior ? pL : (pL && rok);
        const bool okR = interior ? pR : (pR && rok);
        float xly = okL ? hb.y : INF, xlz = okL ? hb.z : INF, xlw = okL ? hb.w : INF;
        float xrx = okR ? hb.x : INF, xry = okR ? hb.y : INF, xrz = okR ? hb.z : INF;

        // ---- horizontal erode: h_j = min(v_{j-2..j+1}) (van Herk) ----
        float vrx = __shfl_down_sync(0xffffffffu, v.x, 1);
        float vwu = __shfl_up_sync  (0xffffffffu, v.w, 1);
        if (lane == 31) vrx = xrx;
        if (lane == 0)  vwu = xlw;
        float4 q;
        q.x = fminf(v.x, v.y); q.y = fminf(v.y, v.z);
        q.z = fminf(v.z, v.w); q.w = fminf(v.w, vrx);
        float qpz = __shfl_up_sync(0xffffffffu, q.z, 1);
        if (lane == 0) qpz = fminf(xlz, xlw);
        float qpw = fminf(vwu, v.x);                      // q.w of lane-1
        float4 h;
        h.x = fminf(qpz, q.x); h.y = fminf(qpw, q.y);
        h.z = fminf(q.x, q.z); h.w = fminf(q.y, q.w);
        float hl  = fminf(fminf(xly, xlz), qpw);   // h @ col c0-1   (lane 0)
        float hr0 = fminf(q.z, fminf(xrx, xry));   // h @ col c0+128 (lane 31)
        float hr1 = fminf(q.w, fminf(xry, xrz));   // h @ col c0+129 (lane 31)

        if (doP) {
            // vertical erode pairwise
            float4 pn;
            pn.x = fminf(h.x, hprev.x); pn.y = fminf(h.y, hprev.y);
            pn.z = fminf(h.z, hprev.z); pn.w = fminf(h.w, hprev.w);
            float pln  = fminf(hl,  hlprev);
            float pr0n = fminf(hr0, hr0prev);
            float pr1n = fminf(hr1, hr1prev);

            if (doEV) {
                const int e = ir - 1;
                const bool eok = interior || ((unsigned)e < 1024u);
                float4 po = pring[par];
                float4 ev;
                if (interior) {
                    ev.x = fminf(po.x, pn.x); ev.y = fminf(po.y, pn.y);
                    ev.z = fminf(po.z, pn.z); ev.w = fminf(po.w, pn.w);
                } else {
                    ev.x = eok ? fminf(po.x, pn.x) : -INF;
                    ev.y = eok ? fminf(po.y, pn.y) : -INF;
                    ev.z = eok ? fminf(po.z, pn.z) : -INF;
                    ev.w = eok ? fminf(po.w, pn.w) : -INF;
                }
                float evL  = (eok && !leftEdge)  ? fminf(plr[par],  pln)  : -INF;
                float evR0 = (eok && !rightEdge) ? fminf(pr0r[par], pr0n) : -INF;
                float evR1 = (eok && !rightEdge) ? fminf(pr1r[par], pr1n) : -INF;

                // horizontal dilate: g_j = max(ev_{j-1..j+2})
                float evwu = __shfl_up_sync  (0xffffffffu, ev.w, 1);
                float evxd = __shfl_down_sync(0xffffffffu, ev.x, 1);
                float evyd = __shfl_down_sync(0xffffffffu, ev.y, 1);
                if (lane == 0)  evwu = evL;
                if (lane == 31) { evxd = evR0; evyd = evR1; }
                float4 r;
                r.x = fmaxf(evwu, ev.x); r.y = fmaxf(ev.x, ev.y);
                r.z = fmaxf(ev.y, ev.z); r.w = fmaxf(ev.z, ev.w);
                float rnx = fmaxf(ev.w, evxd);
                float rny = fmaxf(evxd, evyd);
                float4 g;
                g.x = fmaxf(r.x, r.z); g.y = fmaxf(r.y, r.w);
                g.z = fmaxf(r.z, rnx); g.w = fmaxf(r.w, rny);

                if (doS) {
                    // vertical dilate pairwise
                    float4 sn;
                    sn.x = fmaxf(g.x, gprev.x); sn.y = fmaxf(g.y, gprev.y);
                    sn.z = fmaxf(g.z, gprev.z); sn.w = fmaxf(g.w, gprev.w);
                    if (doOut) {
                        float4 so = sring[par];
                        float4 o4;
                        o4.x = fmaxf(so.x, sn.x); o4.y = fmaxf(so.y, sn.y);
                        o4.z = fmaxf(so.z, sn.z); o4.w = fmaxf(so.w, sn.w);
                        // threshold (monotone => commutes with opening)
                        o4.x = (o4.x >= 0.5f) ? o4.x : 0.0f;
                        o4.y = (o4.y >= 0.5f) ? o4.y : 0.0f;
                        o4.z = (o4.z >= 0.5f) ? o4.z : 0.0f;
                        o4.w = (o4.w >= 0.5f) ? o4.w : 0.0f;
                        const int o = ir - 3;
                        *reinterpret_cast<float4*>(oimg + (size_t)o * 1024 + col) = o4;
                    }
                    sring[par] = sn;
                }
                gprev = g;
            }
            pring[par] = pn; plr[par] = pln;
            pr0r[par] = pr0n; pr1r[par] = pr1n;
        }
        hprev = h; hlprev = hl; hr0prev = hr0; hr1prev = hr1;
    };

    // ---- prefetch pipeline: rows 0..2 in flight ----
    issueRow(0); issueRow(1); issueRow(2);

#define WAIT3() asm volatile("cp.async.wait_group 3;" ::: "memory")

    // prologue (peeled, checked)
    issueRow(3); WAIT3(); step(0, false, false, false, false, false);
    issueRow(4); WAIT3(); step(1, true,  false, false, false, false);
    issueRow(5); WAIT3(); step(2, true,  false, false, false, false);
    issueRow(6); WAIT3(); step(3, true,  true,  false, false, false);
    issueRow(7); WAIT3(); step(4, true,  true,  true,  false, false);
    issueRow(8); WAIT3(); step(5, true,  true,  true,  false, false);

    // interior steady state: t in [6,65]
#pragma unroll 4
    for (int t = 6; t < 66; ++t) {
        issueRow(t + 3);
        WAIT3();
        step(t, true, true, true, true, true);
    }
    // checked tail
#pragma unroll
    for (int t = 66; t < RSTRIP + 6; ++t) {
        issueRow(t + 3);   // clamped, never consumed past t=69; keeps wait depth uniform
        WAIT3();
        step(t, true, true, true, true, false);
    }
#undef WAIT3
}

extern "C" void kernel_launch(void* const* d_in, const int* in_sizes, int n_in,
                              void* d_out, int out_size) {
    const float* score = (const float*)d_in[0];   // 32*1000
    const float* mask  = (const float*)d_in[1];   // 32*1024*1024
    float* out = (float*)d_out;

    float* out_score = out;
    float* out_mask  = out + N_SCORE;

    dim3 grid(1024 / CHUNK, 1024 / (RSTRIP * WARPS), 32);   // (8, 2, 32) = 512 CTAs
    dim3 block(32, WARPS);
    open_kernel<<<grid, block>>>(mask, out_mask, score, out_score);
}